// round 15
// baseline (speedup 1.0000x reference)
#include <cuda_runtime.h>
#include <cuda_bf16.h>
#include <math.h>
#include <stdint.h>

// Problem constants
#define Bv 8
#define Tv 1024
#define Ev 1024
#define Hv 16
#define HDv 64
#define FFv 4096
#define Mv (Bv * Tv)   // 8192 rows

// ---------------------------------------------------------------------------
// Scratch (device globals; no runtime allocation allowed)
// ---------------------------------------------------------------------------
__device__ float g_qkv[(size_t)Mv * 3 * Ev];   // tf32-rounded qkv
__device__ float g_attn[(size_t)Mv * Ev];      // attention out, tf32-rounded
__device__ float g_y1[(size_t)Mv * Ev];
__device__ float g_x1[(size_t)Mv * Ev];        // exact post-LN1 (residual)
__device__ float g_x1r[(size_t)Mv * Ev];       // tf32-rounded post-LN1 (GEMM A)
__device__ float g_h[(size_t)Mv * FFv];        // relu(fc1), tf32-rounded
__device__ float g_y2[(size_t)Mv * Ev];
__device__ float g_xr[(size_t)Mv * Ev];        // tf32-rounded x
__device__ float g_wq[(size_t)3 * Ev * Ev];    // rounded weights
__device__ float g_wo[(size_t)Ev * Ev];
__device__ float g_w1[(size_t)FFv * Ev];
__device__ float g_w2[(size_t)Ev * FFv];
__device__ int   g_len[Bv];

// ---------------------------------------------------------------------------
// Helpers
// ---------------------------------------------------------------------------
__device__ __forceinline__ uint32_t smem_u32(const void* p) {
    uint32_t a;
    asm("{ .reg .u64 t; cvta.to.shared.u64 t, %1; cvt.u32.u64 %0, t; }" : "=r"(a) : "l"(p));
    return a;
}
__device__ __forceinline__ void cp16(uint32_t dst, const void* src) {
    asm volatile("cp.async.cg.shared.global [%0], [%1], 16;" :: "r"(dst), "l"(src));
}
__device__ __forceinline__ float f2tf_f(float f) {
    uint32_t r;
    asm("cvt.rna.tf32.f32 %0, %1;" : "=r"(r) : "f"(f));
    return __uint_as_float(r);
}
__device__ __forceinline__ void mma_tf32(float* c, const uint32_t* a, const uint32_t* b) {
    asm volatile(
        "mma.sync.aligned.m16n8k8.row.col.f32.tf32.tf32.f32 "
        "{%0,%1,%2,%3}, {%4,%5,%6,%7}, {%8,%9}, {%0,%1,%2,%3};"
        : "+f"(c[0]), "+f"(c[1]), "+f"(c[2]), "+f"(c[3])
        : "r"(a[0]), "r"(a[1]), "r"(a[2]), "r"(a[3]), "r"(b[0]), "r"(b[1]));
}

// ---------------------------------------------------------------------------
// tf32 pre-round
// ---------------------------------------------------------------------------
__global__ __launch_bounds__(256) void round_tf32(const float* __restrict__ in,
                                                  float* __restrict__ out, int n4)
{
    int i = blockIdx.x * 256 + threadIdx.x;
    if (i < n4) {
        float4 v = ((const float4*)in)[i];
        v.x = f2tf_f(v.x); v.y = f2tf_f(v.y);
        v.z = f2tf_f(v.z); v.w = f2tf_f(v.w);
        ((float4*)out)[i] = v;
    }
}

// ---------------------------------------------------------------------------
// tf32 mma.sync GEMM: C = A @ W^T + bias (+Res)(ReLU)(rnd)
// BM=128, BN=256, BK=32, 256 threads (2x4 warps, 64x64 warp tiles — same
// proven microkernel as R9/R13), 3-stage cp.async, R9 loop schedule.
// smem bytes/MAC and A-operand L2 traffic both halved vs BN=128.
// ---------------------------------------------------------------------------
#define BKg 32
#define NSTG 3
#define ROWPAD 36
#define TILEA_FL (128 * ROWPAD)                 // 4608 floats
#define TILEB_FL (256 * ROWPAD)                 // 9216 floats
#define STAGE_FL (TILEA_FL + TILEB_FL)          // 13824 floats
#define STAGE_BY (STAGE_FL * 4)                 // 55296 B
#define GSMEM (NSTG * STAGE_BY)                 // 165888 B

__device__ __forceinline__ void load_tiles_g(
    const float* __restrict__ A, const float* __restrict__ W, int K,
    int m0, int n0, int kc, uint32_t sbase, int tid)
{
#pragma unroll
    for (int i = 0; i < 4; i++) {               // A: 128 rows x 8 float4 = 1024
        int idx = tid + i * 256;
        int r = idx >> 3, q = idx & 7;
        cp16(sbase + r * (ROWPAD * 4) + q * 16,
             A + (size_t)(m0 + r) * K + kc + q * 4);
    }
#pragma unroll
    for (int i = 0; i < 8; i++) {               // W: 256 rows x 8 float4 = 2048
        int idx = tid + i * 256;
        int r = idx >> 3, q = idx & 7;
        cp16(sbase + TILEA_FL * 4 + r * (ROWPAD * 4) + q * 16,
             W + (size_t)(n0 + r) * K + kc + q * 4);
    }
}

template<bool ADD_RES, bool RELU, bool ROUND_OUT>
__global__ __launch_bounds__(256, 1) void mma_gemm(
    const float* __restrict__ A, const float* __restrict__ W,
    const float* __restrict__ bias, const float* __restrict__ Res,
    float* __restrict__ C, int M, int N, int K)
{
    extern __shared__ float smf[];
    const uint32_t sb = smem_u32(smf);
    const int tid = threadIdx.x;
    const int wid = tid >> 5, lid = tid & 31;
    const int wm = wid & 1, wn = wid >> 1;      // 2 x 4 warp grid
    const int g = lid >> 2, tg = lid & 3;
    const int m0 = blockIdx.y * 128, n0 = blockIdx.x * 256;

    float acc[4][8][4];
#pragma unroll
    for (int i = 0; i < 4; i++)
#pragma unroll
        for (int j = 0; j < 8; j++)
#pragma unroll
            for (int v = 0; v < 4; v++) acc[i][j][v] = 0.f;

    const int NC = K / BKg;
#pragma unroll
    for (int s = 0; s < NSTG; s++) {
        load_tiles_g(A, W, K, m0, n0, s * BKg, sb + s * STAGE_BY, tid);
        asm volatile("cp.async.commit_group;" ::: "memory");
    }

    for (int c = 0; c < NC; c++) {
        const int s = c % NSTG;
        asm volatile("cp.async.wait_group %0;" :: "n"(NSTG - 1) : "memory");
        __syncthreads();
        const uint32_t* As = (const uint32_t*)(smf + s * STAGE_FL);
        const uint32_t* Ws = As + TILEA_FL;

#pragma unroll
        for (int kk = 0; kk < 4; kk++) {
            const int k0 = kk * 8;
            uint32_t af[4][4];
#pragma unroll
            for (int i = 0; i < 4; i++) {
                int rb = wm * 64 + i * 16 + g;
                af[i][0] = As[rb * ROWPAD + k0 + tg];
                af[i][1] = As[(rb + 8) * ROWPAD + k0 + tg];
                af[i][2] = As[rb * ROWPAD + k0 + tg + 4];
                af[i][3] = As[(rb + 8) * ROWPAD + k0 + tg + 4];
            }
            uint32_t bf[8][2];
#pragma unroll
            for (int j = 0; j < 8; j++) {
                int nb = wn * 64 + j * 8 + g;
                bf[j][0] = Ws[nb * ROWPAD + k0 + tg];
                bf[j][1] = Ws[nb * ROWPAD + k0 + tg + 4];
            }
#pragma unroll
            for (int i = 0; i < 4; i++)
#pragma unroll
                for (int j = 0; j < 8; j++)
                    mma_tf32(acc[i][j], af[i], bf[j]);
        }
        __syncthreads();
        if (c + NSTG < NC) {
            load_tiles_g(A, W, K, m0, n0, (c + NSTG) * BKg, sb + s * STAGE_BY, tid);
        }
        asm volatile("cp.async.commit_group;" ::: "memory");
    }

#pragma unroll
    for (int i = 0; i < 4; i++) {
#pragma unroll
        for (int r = 0; r < 2; r++) {
            const size_t row = (size_t)(m0 + wm * 64 + i * 16 + g + r * 8);
#pragma unroll
            for (int j = 0; j < 8; j++) {
                const int col = n0 + wn * 64 + j * 8 + tg * 2;
                float2 o;
                o.x = acc[i][j][r * 2 + 0];
                o.y = acc[i][j][r * 2 + 1];
                const float2 bb = *(const float2*)(bias + col);
                o.x += bb.x; o.y += bb.y;
                if (ADD_RES) {
                    float2 rr = *(const float2*)(Res + row * N + col);
                    o.x += rr.x; o.y += rr.y;
                }
                if (RELU) { o.x = fmaxf(o.x, 0.f); o.y = fmaxf(o.y, 0.f); }
                if (ROUND_OUT) { o.x = f2tf_f(o.x); o.y = f2tf_f(o.y); }
                *(float2*)(C + row * N + col) = o;
            }
        }
    }
}

// ---------------------------------------------------------------------------
// Padding-mask parsing (unchanged)
// ---------------------------------------------------------------------------
__global__ void len_kernel(const unsigned char* __restrict__ raw)
{
    __shared__ int sh_off, sh_f32;
    const int tid = threadIdx.x;
    if (tid == 0) { sh_off = 0; sh_f32 = 0; }
    __syncthreads();
    int f_off = 0, f_f32 = 0;
    for (int i = tid; i < Bv * Tv; i += 256) {
        unsigned char c = raw[i];
        if (c) {
            if ((i & 3) == 3 && c == 0x3f) f_f32 = 1;
            else if ((i & 3) != 0) f_off = 1;
        }
    }
    if (f_off) atomicOr(&sh_off, 1);
    if (f_f32) atomicOr(&sh_f32, 1);
    __syncthreads();
    const bool byte_mode = (sh_f32 == 0) && (sh_off != 0);
    const int w = tid >> 5, lane = tid & 31;
    if (w < Bv) {
        int cnt = 0;
        for (int t = lane; t < Tv; t += 32) {
            int m;
            if (byte_mode) m = (int)raw[w * Tv + t];
            else           m = ((const int*)raw)[w * Tv + t];
            cnt += (m == 0) ? 1 : 0;
        }
#pragma unroll
        for (int off = 16; off > 0; off >>= 1)
            cnt += __shfl_xor_sync(0xffffffffu, cnt, off);
        if (lane == 0) g_len[w] = cnt;
    }
}

// ---------------------------------------------------------------------------
// Tensor-core flash attention (unchanged from R8/R9)
// ---------------------------------------------------------------------------
#define AQ_OFF 0
#define AK_OFF (64 * 68)
#define AV_OFF (AK_OFF + 2 * 64 * 68)
#define AP_OFF (AV_OFF + 2 * 64 * 72)
#define ATT_FL (AP_OFF + 64 * 68)
#define ATT_SMEM (ATT_FL * 4)                   // 106496 B

__global__ __launch_bounds__(128, 2) void attn_kernel(const float* __restrict__ qkv,
                                                      float* __restrict__ out)
{
    extern __shared__ float sm[];
    const uint32_t sb = smem_u32(sm);
    const int b = blockIdx.z, h = blockIdx.y, qt = blockIdx.x;
    const int tid = threadIdx.x;
    const int wid = tid >> 5, lid = tid & 31;
    const int g = lid >> 2, tg = lid & 3;
    const int len = g_len[b];
    const int q0 = qt * 64;
    const int wrow = wid * 16;
    const size_t base = (size_t)b * Tv * (3 * Ev);

#pragma unroll
    for (int i = 0; i < 8; i++) {
        int idx = tid + i * 128;
        int r = idx >> 4, c4 = (idx & 15) << 2;
        float4 v = *(const float4*)(qkv + base + (size_t)(q0 + r) * (3 * Ev) + h * HDv + c4);
        sm[AQ_OFF + r * 68 + c4 + 0] = v.x * 0.125f;
        sm[AQ_OFF + r * 68 + c4 + 1] = v.y * 0.125f;
        sm[AQ_OFF + r * 68 + c4 + 2] = v.z * 0.125f;
        sm[AQ_OFF + r * 68 + c4 + 3] = v.w * 0.125f;
    }

    const int ktend = min(qt, (len + 63) / 64 - 1);

    {
        const size_t kb = base + (size_t)0 * (3 * Ev) + h * HDv;
#pragma unroll
        for (int i = 0; i < 8; i++) {
            int idx = tid + i * 128;
            int r = idx >> 4, c4 = (idx & 15) << 2;
            cp16(sb + (AK_OFF + r * 68 + c4) * 4, qkv + kb + (size_t)r * (3 * Ev) + Ev + c4);
            cp16(sb + (AV_OFF + r * 72 + c4) * 4, qkv + kb + (size_t)r * (3 * Ev) + 2 * Ev + c4);
        }
        asm volatile("cp.async.commit_group;" ::: "memory");
    }
    __syncthreads();

    uint32_t qf[8][4];
#pragma unroll
    for (int ks = 0; ks < 8; ks++) {
        const uint32_t* Qs = (const uint32_t*)(sm + AQ_OFF);
        qf[ks][0] = Qs[(wrow + g) * 68 + ks * 8 + tg];
        qf[ks][1] = Qs[(wrow + g + 8) * 68 + ks * 8 + tg];
        qf[ks][2] = Qs[(wrow + g) * 68 + ks * 8 + tg + 4];
        qf[ks][3] = Qs[(wrow + g + 8) * 68 + ks * 8 + tg + 4];
    }

    float of[8][4];
#pragma unroll
    for (int j = 0; j < 8; j++)
#pragma unroll
        for (int v = 0; v < 4; v++) of[j][v] = 0.f;
    float m0r = -1e30f, m1r = -1e30f, l0 = 0.f, l1 = 0.f;

    const int qg0 = q0 + wrow + g, qg1 = qg0 + 8;

    for (int kt = 0; kt <= ktend; kt++) {
        const int s = kt & 1;
        if (kt < ktend) {
            const size_t kb = base + (size_t)(kt + 1) * 64 * (3 * Ev) + h * HDv;
            const int s2 = (kt + 1) & 1;
#pragma unroll
            for (int i = 0; i < 8; i++) {
                int idx = tid + i * 128;
                int r = idx >> 4, c4 = (idx & 15) << 2;
                cp16(sb + (AK_OFF + s2 * 64 * 68 + r * 68 + c4) * 4,
                     qkv + kb + (size_t)r * (3 * Ev) + Ev + c4);
                cp16(sb + (AV_OFF + s2 * 64 * 72 + r * 72 + c4) * 4,
                     qkv + kb + (size_t)r * (3 * Ev) + 2 * Ev + c4);
            }
            asm volatile("cp.async.commit_group;" ::: "memory");
            asm volatile("cp.async.wait_group 1;" ::: "memory");
        } else {
            asm volatile("cp.async.wait_group 0;" ::: "memory");
        }
        __syncthreads();

        const uint32_t* Kst = (const uint32_t*)(sm + AK_OFF + s * 64 * 68);
        const uint32_t* Vst = (const uint32_t*)(sm + AV_OFF + s * 64 * 72);
        const int ktb = kt * 64;

        float sf[8][4];
#pragma unroll
        for (int j = 0; j < 8; j++) {
#pragma unroll
            for (int v = 0; v < 4; v++) sf[j][v] = 0.f;
#pragma unroll
            for (int ks = 0; ks < 8; ks++) {
                uint32_t bf[2];
                bf[0] = Kst[(j * 8 + g) * 68 + ks * 8 + tg];
                bf[1] = Kst[(j * 8 + g) * 68 + ks * 8 + tg + 4];
                mma_tf32(sf[j], qf[ks], bf);
            }
        }

#pragma unroll
        for (int j = 0; j < 8; j++) {
            int k0g = ktb + j * 8 + tg * 2;
            int k1g = k0g + 1;
            if (k0g > qg0 || k0g >= len) sf[j][0] = -1e30f;
            if (k1g > qg0 || k1g >= len) sf[j][1] = -1e30f;
            if (k0g > qg1 || k0g >= len) sf[j][2] = -1e30f;
            if (k1g > qg1 || k1g >= len) sf[j][3] = -1e30f;
        }

        float mx0 = -1e30f, mx1 = -1e30f;
#pragma unroll
        for (int j = 0; j < 8; j++) {
            mx0 = fmaxf(mx0, fmaxf(sf[j][0], sf[j][1]));
            mx1 = fmaxf(mx1, fmaxf(sf[j][2], sf[j][3]));
        }
        mx0 = fmaxf(mx0, __shfl_xor_sync(0xffffffffu, mx0, 1));
        mx0 = fmaxf(mx0, __shfl_xor_sync(0xffffffffu, mx0, 2));
        mx1 = fmaxf(mx1, __shfl_xor_sync(0xffffffffu, mx1, 1));
        mx1 = fmaxf(mx1, __shfl_xor_sync(0xffffffffu, mx1, 2));
        const float mn0 = fmaxf(m0r, mx0), mn1 = fmaxf(m1r, mx1);
        const float scl0 = __expf(m0r - mn0), scl1 = __expf(m1r - mn1);
        float rs0 = 0.f, rs1 = 0.f;
#pragma unroll
        for (int j = 0; j < 8; j++) {
            sf[j][0] = __expf(sf[j][0] - mn0);
            sf[j][1] = __expf(sf[j][1] - mn0);
            sf[j][2] = __expf(sf[j][2] - mn1);
            sf[j][3] = __expf(sf[j][3] - mn1);
            rs0 += sf[j][0] + sf[j][1];
            rs1 += sf[j][2] + sf[j][3];
        }
        rs0 += __shfl_xor_sync(0xffffffffu, rs0, 1);
        rs0 += __shfl_xor_sync(0xffffffffu, rs0, 2);
        rs1 += __shfl_xor_sync(0xffffffffu, rs1, 1);
        rs1 += __shfl_xor_sync(0xffffffffu, rs1, 2);
        l0 = l0 * scl0 + rs0;  m0r = mn0;
        l1 = l1 * scl1 + rs1;  m1r = mn1;
#pragma unroll
        for (int j = 0; j < 8; j++) {
            of[j][0] *= scl0; of[j][1] *= scl0;
            of[j][2] *= scl1; of[j][3] *= scl1;
        }

        float* Ps = sm + AP_OFF;
#pragma unroll
        for (int j = 0; j < 8; j++) {
            *(float2*)&Ps[(wrow + g) * 68 + j * 8 + tg * 2] =
                make_float2(f2tf_f(sf[j][0]), f2tf_f(sf[j][1]));
            *(float2*)&Ps[(wrow + g + 8) * 68 + j * 8 + tg * 2] =
                make_float2(f2tf_f(sf[j][2]), f2tf_f(sf[j][3]));
        }
        __syncwarp();

        const uint32_t* Pu = (const uint32_t*)(sm + AP_OFF);
#pragma unroll
        for (int ks = 0; ks < 8; ks++) {
            uint32_t pa[4];
            pa[0] = Pu[(wrow + g) * 68 + ks * 8 + tg];
            pa[1] = Pu[(wrow + g + 8) * 68 + ks * 8 + tg];
            pa[2] = Pu[(wrow + g) * 68 + ks * 8 + tg + 4];
            pa[3] = Pu[(wrow + g + 8) * 68 + ks * 8 + tg + 4];
#pragma unroll
            for (int j = 0; j < 8; j++) {
                uint32_t bf[2];
                bf[0] = Vst[(ks * 8 + tg) * 72 + j * 8 + g];
                bf[1] = Vst[(ks * 8 + tg + 4) * 72 + j * 8 + g];
                mma_tf32(of[j], pa, bf);
            }
        }
        __syncthreads();
    }

    const float inv0 = 1.f / l0, inv1 = 1.f / l1;
    const size_t row0 = (size_t)b * Tv + qg0;
    const size_t row1 = (size_t)b * Tv + qg1;
#pragma unroll
    for (int j = 0; j < 8; j++) {
        const int col = h * HDv + j * 8 + tg * 2;
        *(float2*)(out + row0 * Ev + col) =
            make_float2(f2tf_f(of[j][0] * inv0), f2tf_f(of[j][1] * inv0));
        *(float2*)(out + row1 * Ev + col) =
            make_float2(f2tf_f(of[j][2] * inv1), f2tf_f(of[j][3] * inv1));
    }
}

// ---------------------------------------------------------------------------
// LayerNorm: warp-per-row, 8 rows per 256-thread block. No block syncs.
// ---------------------------------------------------------------------------
template<bool DUAL>
__global__ __launch_bounds__(256) void ln_kernel(const float* __restrict__ X,
                                                 const float* __restrict__ w,
                                                 const float* __restrict__ bvec,
                                                 float* __restrict__ out,
                                                 float* __restrict__ out_r)
{
    const int wid = threadIdx.x >> 5, lane = threadIdx.x & 31;
    const size_t row = (size_t)blockIdx.x * 8 + wid;
    const float* xp = X + row * Ev;

    float4 v[8];
    float s = 0.f, q = 0.f;
#pragma unroll
    for (int i = 0; i < 8; i++) {
        v[i] = *(const float4*)(xp + (i * 32 + lane) * 4);
        s += v[i].x + v[i].y + v[i].z + v[i].w;
        q += v[i].x * v[i].x + v[i].y * v[i].y + v[i].z * v[i].z + v[i].w * v[i].w;
    }
#pragma unroll
    for (int off = 16; off > 0; off >>= 1) {
        s += __shfl_xor_sync(0xffffffffu, s, off);
        q += __shfl_xor_sync(0xffffffffu, q, off);
    }
    const float u = s * (1.f / 1024.f);
    const float var = fmaxf(q * (1.f / 1024.f) - u * u, 0.f);
    const float rstd = rsqrtf(var + 1e-12f);

#pragma unroll
    for (int i = 0; i < 8; i++) {
        const int c = (i * 32 + lane) * 4;
        float4 ww = *(const float4*)(w + c);
        float4 bb = *(const float4*)(bvec + c);
        float4 o;
        o.x = (v[i].x - u) * rstd * ww.x + bb.x;
        o.y = (v[i].y - u) * rstd * ww.y + bb.y;
        o.z = (v[i].z - u) * rstd * ww.z + bb.z;
        o.w = (v[i].w - u) * rstd * ww.w + bb.w;
        *(float4*)(out + row * Ev + c) = o;
        if (DUAL) {
            float4 r = make_float4(f2tf_f(o.x), f2tf_f(o.y), f2tf_f(o.z), f2tf_f(o.w));
            *(float4*)(out_r + row * Ev + c) = r;
        }
    }
}

// ---------------------------------------------------------------------------
// Launch
// ---------------------------------------------------------------------------
extern "C" void kernel_launch(void* const* d_in, const int* in_sizes, int n_in,
                              void* d_out, int out_size)
{
    const float* x     = (const float*)d_in[0];
    const float* in_w  = (const float*)d_in[1];
    const float* in_b  = (const float*)d_in[2];
    const float* out_w = (const float*)d_in[3];
    const float* out_b = (const float*)d_in[4];
    const float* fc1_w = (const float*)d_in[5];
    const float* fc1_b = (const float*)d_in[6];
    const float* fc2_w = (const float*)d_in[7];
    const float* fc2_b = (const float*)d_in[8];
    const float* ln1_w = (const float*)d_in[9];
    const float* ln1_b = (const float*)d_in[10];
    const float* ln2_w = (const float*)d_in[11];
    const float* ln2_b = (const float*)d_in[12];

    const unsigned char* pmask = (const unsigned char*)d_in[13];
    for (int i = 0; i < n_in; i++)
        if (in_sizes[i] == Bv * Tv) { pmask = (const unsigned char*)d_in[i]; break; }

    float *qkv, *attn, *y1, *x1, *x1r, *hb, *y2, *xr, *wq, *wo, *w1, *w2;
    cudaGetSymbolAddress((void**)&qkv,  g_qkv);
    cudaGetSymbolAddress((void**)&attn, g_attn);
    cudaGetSymbolAddress((void**)&y1,   g_y1);
    cudaGetSymbolAddress((void**)&x1,   g_x1);
    cudaGetSymbolAddress((void**)&x1r,  g_x1r);
    cudaGetSymbolAddress((void**)&hb,   g_h);
    cudaGetSymbolAddress((void**)&y2,   g_y2);
    cudaGetSymbolAddress((void**)&xr,   g_xr);
    cudaGetSymbolAddress((void**)&wq,   g_wq);
    cudaGetSymbolAddress((void**)&wo,   g_wo);
    cudaGetSymbolAddress((void**)&w1,   g_w1);
    cudaGetSymbolAddress((void**)&w2,   g_w2);

    cudaFuncSetAttribute(attn_kernel, cudaFuncAttributeMaxDynamicSharedMemorySize, ATT_SMEM);
    cudaFuncSetAttribute(mma_gemm<false, false, true >, cudaFuncAttributeMaxDynamicSharedMemorySize, GSMEM);
    cudaFuncSetAttribute(mma_gemm<true,  false, false>, cudaFuncAttributeMaxDynamicSharedMemorySize, GSMEM);
    cudaFuncSetAttribute(mma_gemm<false, true,  true >, cudaFuncAttributeMaxDynamicSharedMemorySize, GSMEM);

    len_kernel<<<1, 256>>>(pmask);

    // tf32 pre-rounding (exact rna, once per element)
    round_tf32<<<(Mv * Ev / 4 + 255) / 256, 256>>>(x, xr, Mv * Ev / 4);
    round_tf32<<<(3 * Ev * Ev / 4 + 255) / 256, 256>>>(in_w, wq, 3 * Ev * Ev / 4);
    round_tf32<<<(Ev * Ev / 4 + 255) / 256, 256>>>(out_w, wo, Ev * Ev / 4);
    round_tf32<<<(FFv * Ev / 4 + 255) / 256, 256>>>(fc1_w, w1, FFv * Ev / 4);
    round_tf32<<<(Ev * FFv / 4 + 255) / 256, 256>>>(fc2_w, w2, Ev * FFv / 4);

    // QKV projection (output tf32-rounded: feeds tensor-core attention)
    mma_gemm<false, false, true><<<dim3(3 * Ev / 256, Mv / 128), 256, GSMEM>>>(
        xr, wq, in_b, nullptr, qkv, Mv, 3 * Ev, Ev);

    // Tensor-core flash attention (causal + key padding); output tf32-rounded
    attn_kernel<<<dim3(Tv / 64, Hv, Bv), 128, ATT_SMEM>>>(qkv, attn);

    // Out projection + residual (residual = exact x)
    mma_gemm<true, false, false><<<dim3(Ev / 256, Mv / 128), 256, GSMEM>>>(
        attn, wo, out_b, x, y1, Mv, Ev, Ev);
    ln_kernel<true><<<Mv / 8, 256>>>(y1, ln1_w, ln1_b, x1, x1r);

    // FFN
    mma_gemm<false, true, true><<<dim3(FFv / 256, Mv / 128), 256, GSMEM>>>(
        x1r, w1, fc1_b, nullptr, hb, Mv, FFv, Ev);
    mma_gemm<true, false, false><<<dim3(Ev / 256, Mv / 128), 256, GSMEM>>>(
        hb, w2, fc2_b, x1, y2, Mv, Ev, FFv);
    ln_kernel<false><<<Mv / 8, 256>>>(y2, ln2_w, ln2_b, (float*)d_out, nullptr);

    (void)in_sizes; (void)n_in; (void)out_size;
}

// round 16
// speedup vs baseline: 1.0556x; 1.0556x over previous
#include <cuda_runtime.h>
#include <cuda_bf16.h>
#include <math.h>
#include <stdint.h>

// Problem constants
#define Bv 8
#define Tv 1024
#define Ev 1024
#define Hv 16
#define HDv 64
#define FFv 4096
#define Mv (Bv * Tv)   // 8192 rows

// ---------------------------------------------------------------------------
// Scratch (device globals; no runtime allocation allowed)
// ---------------------------------------------------------------------------
__device__ float g_qkv[(size_t)Mv * 3 * Ev];   // tf32-rounded qkv
__device__ float g_attn[(size_t)Mv * Ev];      // attention out, tf32-rounded
__device__ float g_y1[(size_t)Mv * Ev];
__device__ float g_x1[(size_t)Mv * Ev];        // exact post-LN1 (residual)
__device__ float g_x1r[(size_t)Mv * Ev];       // tf32-rounded post-LN1 (GEMM A)
__device__ float g_h[(size_t)Mv * FFv];        // relu(fc1), tf32-rounded
__device__ float g_y2[(size_t)Mv * Ev];
__device__ float g_xr[(size_t)Mv * Ev];        // tf32-rounded x
__device__ float g_wq[(size_t)3 * Ev * Ev];    // rounded weights
__device__ float g_wo[(size_t)Ev * Ev];
__device__ float g_w1[(size_t)FFv * Ev];
__device__ float g_w2[(size_t)Ev * FFv];
__device__ int   g_len[Bv];

// ---------------------------------------------------------------------------
// Helpers
// ---------------------------------------------------------------------------
__device__ __forceinline__ uint32_t smem_u32(const void* p) {
    uint32_t a;
    asm("{ .reg .u64 t; cvta.to.shared.u64 t, %1; cvt.u32.u64 %0, t; }" : "=r"(a) : "l"(p));
    return a;
}
__device__ __forceinline__ void cp16(uint32_t dst, const void* src) {
    asm volatile("cp.async.cg.shared.global [%0], [%1], 16;" :: "r"(dst), "l"(src));
}
__device__ __forceinline__ float f2tf_f(float f) {
    uint32_t r;
    asm("cvt.rna.tf32.f32 %0, %1;" : "=r"(r) : "f"(f));
    return __uint_as_float(r);
}
__device__ __forceinline__ void mma_tf32(float* c, const uint32_t* a, const uint32_t* b) {
    asm volatile(
        "mma.sync.aligned.m16n8k8.row.col.f32.tf32.tf32.f32 "
        "{%0,%1,%2,%3}, {%4,%5,%6,%7}, {%8,%9}, {%0,%1,%2,%3};"
        : "+f"(c[0]), "+f"(c[1]), "+f"(c[2]), "+f"(c[3])
        : "r"(a[0]), "r"(a[1]), "r"(a[2]), "r"(a[3]), "r"(b[0]), "r"(b[1]));
}

// ---------------------------------------------------------------------------
// Fused tf32 pre-round: one launch for all 5 tensors (x + 4 weights).
// Segment sizes in float4 units.
// ---------------------------------------------------------------------------
#define N4_X   (Mv * Ev / 4)            // 2097152
#define N4_WQ  (3 * Ev * Ev / 4)        //  786432
#define N4_WO  (Ev * Ev / 4)            //  262144
#define N4_W1  (FFv * Ev / 4)           // 1048576
#define N4_W2  (Ev * FFv / 4)           // 1048576
#define N4_TOT (N4_X + N4_WQ + N4_WO + N4_W1 + N4_W2)

__global__ __launch_bounds__(256) void round_all(
    const float* __restrict__ x,  float* __restrict__ xr,
    const float* __restrict__ wq, float* __restrict__ wqo,
    const float* __restrict__ wo, float* __restrict__ woo,
    const float* __restrict__ w1, float* __restrict__ w1o,
    const float* __restrict__ w2, float* __restrict__ w2o)
{
    int i = blockIdx.x * 256 + threadIdx.x;
    if (i >= N4_TOT) return;
    const float4* src;
    float4* dst;
    if (i < N4_X)                              { src = (const float4*)x;  dst = (float4*)xr; }
    else if ((i -= N4_X) < N4_WQ)              { src = (const float4*)wq; dst = (float4*)wqo; }
    else if ((i -= N4_WQ) < N4_WO)             { src = (const float4*)wo; dst = (float4*)woo; }
    else if ((i -= N4_WO) < N4_W1)             { src = (const float4*)w1; dst = (float4*)w1o; }
    else                { i -= N4_W1;            src = (const float4*)w2; dst = (float4*)w2o; }
    float4 v = src[i];
    v.x = f2tf_f(v.x); v.y = f2tf_f(v.y);
    v.z = f2tf_f(v.z); v.w = f2tf_f(v.w);
    dst[i] = v;
}

// ---------------------------------------------------------------------------
// tf32 mma.sync GEMM (R13 — proven fastest): C = A @ W^T + bias (+Res)(ReLU)
// (rnd). BM=BN=128, BK=32, 128 threads (2x2 warps, 64x64 warp tiles),
// 3-stage cp.async pipeline, loads issued after compute, 2 CTAs/SM.
// ---------------------------------------------------------------------------
#define BKg 32
#define NSTG 3
#define ROWPAD 36
#define TILE_FL (128 * ROWPAD)
#define STAGE_FL (2 * TILE_FL)
#define STAGE_BY (STAGE_FL * 4)
#define GSMEM (NSTG * STAGE_BY)                 // 110592 B

__device__ __forceinline__ void load_tiles_g(
    const float* __restrict__ A, const float* __restrict__ W, int K,
    int m0, int n0, int kc, uint32_t sbase, int tid)
{
#pragma unroll
    for (int i = 0; i < 8; i++) {
        int idx = tid + i * 128;
        int r = idx >> 3, q = idx & 7;
        cp16(sbase + r * (ROWPAD * 4) + q * 16,
             A + (size_t)(m0 + r) * K + kc + q * 4);
    }
#pragma unroll
    for (int i = 0; i < 8; i++) {
        int idx = tid + i * 128;
        int r = idx >> 3, q = idx & 7;
        cp16(sbase + TILE_FL * 4 + r * (ROWPAD * 4) + q * 16,
             W + (size_t)(n0 + r) * K + kc + q * 4);
    }
}

template<bool ADD_RES, bool RELU, bool ROUND_OUT>
__global__ __launch_bounds__(128, 2) void mma_gemm(
    const float* __restrict__ A, const float* __restrict__ W,
    const float* __restrict__ bias, const float* __restrict__ Res,
    float* __restrict__ C, int M, int N, int K)
{
    extern __shared__ float smf[];
    const uint32_t sb = smem_u32(smf);
    const int tid = threadIdx.x;
    const int wid = tid >> 5, lid = tid & 31;
    const int wm = wid & 1, wn = wid >> 1;
    const int g = lid >> 2, tg = lid & 3;
    const int m0 = blockIdx.y * 128, n0 = blockIdx.x * 128;

    float acc[4][8][4];
#pragma unroll
    for (int i = 0; i < 4; i++)
#pragma unroll
        for (int j = 0; j < 8; j++)
#pragma unroll
            for (int v = 0; v < 4; v++) acc[i][j][v] = 0.f;

    const int NC = K / BKg;
#pragma unroll
    for (int s = 0; s < NSTG; s++) {
        load_tiles_g(A, W, K, m0, n0, s * BKg, sb + s * STAGE_BY, tid);
        asm volatile("cp.async.commit_group;" ::: "memory");
    }

    for (int c = 0; c < NC; c++) {
        const int s = c % NSTG;
        asm volatile("cp.async.wait_group %0;" :: "n"(NSTG - 1) : "memory");
        __syncthreads();
        const uint32_t* As = (const uint32_t*)(smf + s * STAGE_FL);
        const uint32_t* Ws = As + TILE_FL;

#pragma unroll
        for (int kk = 0; kk < 4; kk++) {
            const int k0 = kk * 8;
            uint32_t af[4][4];
#pragma unroll
            for (int i = 0; i < 4; i++) {
                int rb = wm * 64 + i * 16 + g;
                af[i][0] = As[rb * ROWPAD + k0 + tg];
                af[i][1] = As[(rb + 8) * ROWPAD + k0 + tg];
                af[i][2] = As[rb * ROWPAD + k0 + tg + 4];
                af[i][3] = As[(rb + 8) * ROWPAD + k0 + tg + 4];
            }
            uint32_t bf[8][2];
#pragma unroll
            for (int j = 0; j < 8; j++) {
                int nb = wn * 64 + j * 8 + g;
                bf[j][0] = Ws[nb * ROWPAD + k0 + tg];
                bf[j][1] = Ws[nb * ROWPAD + k0 + tg + 4];
            }
#pragma unroll
            for (int i = 0; i < 4; i++)
#pragma unroll
                for (int j = 0; j < 8; j++)
                    mma_tf32(acc[i][j], af[i], bf[j]);
        }
        __syncthreads();
        if (c + NSTG < NC) {
            load_tiles_g(A, W, K, m0, n0, (c + NSTG) * BKg, sb + s * STAGE_BY, tid);
        }
        asm volatile("cp.async.commit_group;" ::: "memory");
    }

#pragma unroll
    for (int i = 0; i < 4; i++) {
#pragma unroll
        for (int r = 0; r < 2; r++) {
            const size_t row = (size_t)(m0 + wm * 64 + i * 16 + g + r * 8);
#pragma unroll
            for (int j = 0; j < 8; j++) {
                const int col = n0 + wn * 64 + j * 8 + tg * 2;
                float2 o;
                o.x = acc[i][j][r * 2 + 0];
                o.y = acc[i][j][r * 2 + 1];
                const float2 bb = *(const float2*)(bias + col);
                o.x += bb.x; o.y += bb.y;
                if (ADD_RES) {
                    float2 rr = *(const float2*)(Res + row * N + col);
                    o.x += rr.x; o.y += rr.y;
                }
                if (RELU) { o.x = fmaxf(o.x, 0.f); o.y = fmaxf(o.y, 0.f); }
                if (ROUND_OUT) { o.x = f2tf_f(o.x); o.y = f2tf_f(o.y); }
                *(float2*)(C + row * N + col) = o;
            }
        }
    }
}

// ---------------------------------------------------------------------------
// Padding-mask parsing (unchanged)
// ---------------------------------------------------------------------------
__global__ void len_kernel(const unsigned char* __restrict__ raw)
{
    __shared__ int sh_off, sh_f32;
    const int tid = threadIdx.x;
    if (tid == 0) { sh_off = 0; sh_f32 = 0; }
    __syncthreads();
    int f_off = 0, f_f32 = 0;
    for (int i = tid; i < Bv * Tv; i += 256) {
        unsigned char c = raw[i];
        if (c) {
            if ((i & 3) == 3 && c == 0x3f) f_f32 = 1;
            else if ((i & 3) != 0) f_off = 1;
        }
    }
    if (f_off) atomicOr(&sh_off, 1);
    if (f_f32) atomicOr(&sh_f32, 1);
    __syncthreads();
    const bool byte_mode = (sh_f32 == 0) && (sh_off != 0);
    const int w = tid >> 5, lane = tid & 31;
    if (w < Bv) {
        int cnt = 0;
        for (int t = lane; t < Tv; t += 32) {
            int m;
            if (byte_mode) m = (int)raw[w * Tv + t];
            else           m = ((const int*)raw)[w * Tv + t];
            cnt += (m == 0) ? 1 : 0;
        }
#pragma unroll
        for (int off = 16; off > 0; off >>= 1)
            cnt += __shfl_xor_sync(0xffffffffu, cnt, off);
        if (lane == 0) g_len[w] = cnt;
    }
}

// ---------------------------------------------------------------------------
// Tensor-core flash attention (unchanged from R8/R9/R13)
// ---------------------------------------------------------------------------
#define AQ_OFF 0
#define AK_OFF (64 * 68)
#define AV_OFF (AK_OFF + 2 * 64 * 68)
#define AP_OFF (AV_OFF + 2 * 64 * 72)
#define ATT_FL (AP_OFF + 64 * 68)
#define ATT_SMEM (ATT_FL * 4)                   // 106496 B

__global__ __launch_bounds__(128, 2) void attn_kernel(const float* __restrict__ qkv,
                                                      float* __restrict__ out)
{
    extern __shared__ float sm[];
    const uint32_t sb = smem_u32(sm);
    const int b = blockIdx.z, h = blockIdx.y, qt = blockIdx.x;
    const int tid = threadIdx.x;
    const int wid = tid >> 5, lid = tid & 31;
    const int g = lid >> 2, tg = lid & 3;
    const int len = g_len[b];
    const int q0 = qt * 64;
    const int wrow = wid * 16;
    const size_t base = (size_t)b * Tv * (3 * Ev);

#pragma unroll
    for (int i = 0; i < 8; i++) {
        int idx = tid + i * 128;
        int r = idx >> 4, c4 = (idx & 15) << 2;
        float4 v = *(const float4*)(qkv + base + (size_t)(q0 + r) * (3 * Ev) + h * HDv + c4);
        sm[AQ_OFF + r * 68 + c4 + 0] = v.x * 0.125f;
        sm[AQ_OFF + r * 68 + c4 + 1] = v.y * 0.125f;
        sm[AQ_OFF + r * 68 + c4 + 2] = v.z * 0.125f;
        sm[AQ_OFF + r * 68 + c4 + 3] = v.w * 0.125f;
    }

    const int ktend = min(qt, (len + 63) / 64 - 1);

    {
        const size_t kb = base + (size_t)0 * (3 * Ev) + h * HDv;
#pragma unroll
        for (int i = 0; i < 8; i++) {
            int idx = tid + i * 128;
            int r = idx >> 4, c4 = (idx & 15) << 2;
            cp16(sb + (AK_OFF + r * 68 + c4) * 4, qkv + kb + (size_t)r * (3 * Ev) + Ev + c4);
            cp16(sb + (AV_OFF + r * 72 + c4) * 4, qkv + kb + (size_t)r * (3 * Ev) + 2 * Ev + c4);
        }
        asm volatile("cp.async.commit_group;" ::: "memory");
    }
    __syncthreads();

    uint32_t qf[8][4];
#pragma unroll
    for (int ks = 0; ks < 8; ks++) {
        const uint32_t* Qs = (const uint32_t*)(sm + AQ_OFF);
        qf[ks][0] = Qs[(wrow + g) * 68 + ks * 8 + tg];
        qf[ks][1] = Qs[(wrow + g + 8) * 68 + ks * 8 + tg];
        qf[ks][2] = Qs[(wrow + g) * 68 + ks * 8 + tg + 4];
        qf[ks][3] = Qs[(wrow + g + 8) * 68 + ks * 8 + tg + 4];
    }

    float of[8][4];
#pragma unroll
    for (int j = 0; j < 8; j++)
#pragma unroll
        for (int v = 0; v < 4; v++) of[j][v] = 0.f;
    float m0r = -1e30f, m1r = -1e30f, l0 = 0.f, l1 = 0.f;

    const int qg0 = q0 + wrow + g, qg1 = qg0 + 8;

    for (int kt = 0; kt <= ktend; kt++) {
        const int s = kt & 1;
        if (kt < ktend) {
            const size_t kb = base + (size_t)(kt + 1) * 64 * (3 * Ev) + h * HDv;
            const int s2 = (kt + 1) & 1;
#pragma unroll
            for (int i = 0; i < 8; i++) {
                int idx = tid + i * 128;
                int r = idx >> 4, c4 = (idx & 15) << 2;
                cp16(sb + (AK_OFF + s2 * 64 * 68 + r * 68 + c4) * 4,
                     qkv + kb + (size_t)r * (3 * Ev) + Ev + c4);
                cp16(sb + (AV_OFF + s2 * 64 * 72 + r * 72 + c4) * 4,
                     qkv + kb + (size_t)r * (3 * Ev) + 2 * Ev + c4);
            }
            asm volatile("cp.async.commit_group;" ::: "memory");
            asm volatile("cp.async.wait_group 1;" ::: "memory");
        } else {
            asm volatile("cp.async.wait_group 0;" ::: "memory");
        }
        __syncthreads();

        const uint32_t* Kst = (const uint32_t*)(sm + AK_OFF + s * 64 * 68);
        const uint32_t* Vst = (const uint32_t*)(sm + AV_OFF + s * 64 * 72);
        const int ktb = kt * 64;

        float sf[8][4];
#pragma unroll
        for (int j = 0; j < 8; j++) {
#pragma unroll
            for (int v = 0; v < 4; v++) sf[j][v] = 0.f;
#pragma unroll
            for (int ks = 0; ks < 8; ks++) {
                uint32_t bf[2];
                bf[0] = Kst[(j * 8 + g) * 68 + ks * 8 + tg];
                bf[1] = Kst[(j * 8 + g) * 68 + ks * 8 + tg + 4];
                mma_tf32(sf[j], qf[ks], bf);
            }
        }

#pragma unroll
        for (int j = 0; j < 8; j++) {
            int k0g = ktb + j * 8 + tg * 2;
            int k1g = k0g + 1;
            if (k0g > qg0 || k0g >= len) sf[j][0] = -1e30f;
            if (k1g > qg0 || k1g >= len) sf[j][1] = -1e30f;
            if (k0g > qg1 || k0g >= len) sf[j][2] = -1e30f;
            if (k1g > qg1 || k1g >= len) sf[j][3] = -1e30f;
        }

        float mx0 = -1e30f, mx1 = -1e30f;
#pragma unroll
        for (int j = 0; j < 8; j++) {
            mx0 = fmaxf(mx0, fmaxf(sf[j][0], sf[j][1]));
            mx1 = fmaxf(mx1, fmaxf(sf[j][2], sf[j][3]));
        }
        mx0 = fmaxf(mx0, __shfl_xor_sync(0xffffffffu, mx0, 1));
        mx0 = fmaxf(mx0, __shfl_xor_sync(0xffffffffu, mx0, 2));
        mx1 = fmaxf(mx1, __shfl_xor_sync(0xffffffffu, mx1, 1));
        mx1 = fmaxf(mx1, __shfl_xor_sync(0xffffffffu, mx1, 2));
        const float mn0 = fmaxf(m0r, mx0), mn1 = fmaxf(m1r, mx1);
        const float scl0 = __expf(m0r - mn0), scl1 = __expf(m1r - mn1);
        float rs0 = 0.f, rs1 = 0.f;
#pragma unroll
        for (int j = 0; j < 8; j++) {
            sf[j][0] = __expf(sf[j][0] - mn0);
            sf[j][1] = __expf(sf[j][1] - mn0);
            sf[j][2] = __expf(sf[j][2] - mn1);
            sf[j][3] = __expf(sf[j][3] - mn1);
            rs0 += sf[j][0] + sf[j][1];
            rs1 += sf[j][2] + sf[j][3];
        }
        rs0 += __shfl_xor_sync(0xffffffffu, rs0, 1);
        rs0 += __shfl_xor_sync(0xffffffffu, rs0, 2);
        rs1 += __shfl_xor_sync(0xffffffffu, rs1, 1);
        rs1 += __shfl_xor_sync(0xffffffffu, rs1, 2);
        l0 = l0 * scl0 + rs0;  m0r = mn0;
        l1 = l1 * scl1 + rs1;  m1r = mn1;
#pragma unroll
        for (int j = 0; j < 8; j++) {
            of[j][0] *= scl0; of[j][1] *= scl0;
            of[j][2] *= scl1; of[j][3] *= scl1;
        }

        float* Ps = sm + AP_OFF;
#pragma unroll
        for (int j = 0; j < 8; j++) {
            *(float2*)&Ps[(wrow + g) * 68 + j * 8 + tg * 2] =
                make_float2(f2tf_f(sf[j][0]), f2tf_f(sf[j][1]));
            *(float2*)&Ps[(wrow + g + 8) * 68 + j * 8 + tg * 2] =
                make_float2(f2tf_f(sf[j][2]), f2tf_f(sf[j][3]));
        }
        __syncwarp();

        const uint32_t* Pu = (const uint32_t*)(sm + AP_OFF);
#pragma unroll
        for (int ks = 0; ks < 8; ks++) {
            uint32_t pa[4];
            pa[0] = Pu[(wrow + g) * 68 + ks * 8 + tg];
            pa[1] = Pu[(wrow + g + 8) * 68 + ks * 8 + tg];
            pa[2] = Pu[(wrow + g) * 68 + ks * 8 + tg + 4];
            pa[3] = Pu[(wrow + g + 8) * 68 + ks * 8 + tg + 4];
#pragma unroll
            for (int j = 0; j < 8; j++) {
                uint32_t bf[2];
                bf[0] = Vst[(ks * 8 + tg) * 72 + j * 8 + g];
                bf[1] = Vst[(ks * 8 + tg + 4) * 72 + j * 8 + g];
                mma_tf32(of[j], pa, bf);
            }
        }
        __syncthreads();
    }

    const float inv0 = 1.f / l0, inv1 = 1.f / l1;
    const size_t row0 = (size_t)b * Tv + qg0;
    const size_t row1 = (size_t)b * Tv + qg1;
#pragma unroll
    for (int j = 0; j < 8; j++) {
        const int col = h * HDv + j * 8 + tg * 2;
        *(float2*)(out + row0 * Ev + col) =
            make_float2(f2tf_f(of[j][0] * inv0), f2tf_f(of[j][1] * inv0));
        *(float2*)(out + row1 * Ev + col) =
            make_float2(f2tf_f(of[j][2] * inv1), f2tf_f(of[j][3] * inv1));
    }
}

// ---------------------------------------------------------------------------
// LayerNorm: warp-per-row, 8 rows per 256-thread block. No block syncs.
// ---------------------------------------------------------------------------
template<bool DUAL>
__global__ __launch_bounds__(256) void ln_kernel(const float* __restrict__ X,
                                                 const float* __restrict__ w,
                                                 const float* __restrict__ bvec,
                                                 float* __restrict__ out,
                                                 float* __restrict__ out_r)
{
    const int wid = threadIdx.x >> 5, lane = threadIdx.x & 31;
    const size_t row = (size_t)blockIdx.x * 8 + wid;
    const float* xp = X + row * Ev;

    float4 v[8];
    float s = 0.f, q = 0.f;
#pragma unroll
    for (int i = 0; i < 8; i++) {
        v[i] = *(const float4*)(xp + (i * 32 + lane) * 4);
        s += v[i].x + v[i].y + v[i].z + v[i].w;
        q += v[i].x * v[i].x + v[i].y * v[i].y + v[i].z * v[i].z + v[i].w * v[i].w;
    }
#pragma unroll
    for (int off = 16; off > 0; off >>= 1) {
        s += __shfl_xor_sync(0xffffffffu, s, off);
        q += __shfl_xor_sync(0xffffffffu, q, off);
    }
    const float u = s * (1.f / 1024.f);
    const float var = fmaxf(q * (1.f / 1024.f) - u * u, 0.f);
    const float rstd = rsqrtf(var + 1e-12f);

#pragma unroll
    for (int i = 0; i < 8; i++) {
        const int c = (i * 32 + lane) * 4;
        float4 ww = *(const float4*)(w + c);
        float4 bb = *(const float4*)(bvec + c);
        float4 o;
        o.x = (v[i].x - u) * rstd * ww.x + bb.x;
        o.y = (v[i].y - u) * rstd * ww.y + bb.y;
        o.z = (v[i].z - u) * rstd * ww.z + bb.z;
        o.w = (v[i].w - u) * rstd * ww.w + bb.w;
        *(float4*)(out + row * Ev + c) = o;
        if (DUAL) {
            float4 r = make_float4(f2tf_f(o.x), f2tf_f(o.y), f2tf_f(o.z), f2tf_f(o.w));
            *(float4*)(out_r + row * Ev + c) = r;
        }
    }
}

// ---------------------------------------------------------------------------
// Launch
// ---------------------------------------------------------------------------
extern "C" void kernel_launch(void* const* d_in, const int* in_sizes, int n_in,
                              void* d_out, int out_size)
{
    const float* x     = (const float*)d_in[0];
    const float* in_w  = (const float*)d_in[1];
    const float* in_b  = (const float*)d_in[2];
    const float* out_w = (const float*)d_in[3];
    const float* out_b = (const float*)d_in[4];
    const float* fc1_w = (const float*)d_in[5];
    const float* fc1_b = (const float*)d_in[6];
    const float* fc2_w = (const float*)d_in[7];
    const float* fc2_b = (const float*)d_in[8];
    const float* ln1_w = (const float*)d_in[9];
    const float* ln1_b = (const float*)d_in[10];
    const float* ln2_w = (const float*)d_in[11];
    const float* ln2_b = (const float*)d_in[12];

    const unsigned char* pmask = (const unsigned char*)d_in[13];
    for (int i = 0; i < n_in; i++)
        if (in_sizes[i] == Bv * Tv) { pmask = (const unsigned char*)d_in[i]; break; }

    float *qkv, *attn, *y1, *x1, *x1r, *hb, *y2, *xr, *wq, *wo, *w1, *w2;
    cudaGetSymbolAddress((void**)&qkv,  g_qkv);
    cudaGetSymbolAddress((void**)&attn, g_attn);
    cudaGetSymbolAddress((void**)&y1,   g_y1);
    cudaGetSymbolAddress((void**)&x1,   g_x1);
    cudaGetSymbolAddress((void**)&x1r,  g_x1r);
    cudaGetSymbolAddress((void**)&hb,   g_h);
    cudaGetSymbolAddress((void**)&y2,   g_y2);
    cudaGetSymbolAddress((void**)&xr,   g_xr);
    cudaGetSymbolAddress((void**)&wq,   g_wq);
    cudaGetSymbolAddress((void**)&wo,   g_wo);
    cudaGetSymbolAddress((void**)&w1,   g_w1);
    cudaGetSymbolAddress((void**)&w2,   g_w2);

    cudaFuncSetAttribute(attn_kernel, cudaFuncAttributeMaxDynamicSharedMemorySize, ATT_SMEM);
    cudaFuncSetAttribute(mma_gemm<false, false, true >, cudaFuncAttributeMaxDynamicSharedMemorySize, GSMEM);
    cudaFuncSetAttribute(mma_gemm<true,  false, false>, cudaFuncAttributeMaxDynamicSharedMemorySize, GSMEM);
    cudaFuncSetAttribute(mma_gemm<false, true,  true >, cudaFuncAttributeMaxDynamicSharedMemorySize, GSMEM);

    len_kernel<<<1, 256>>>(pmask);

    // Fused tf32 pre-rounding (exact rna, once per element, ONE launch)
    round_all<<<(N4_TOT + 255) / 256, 256>>>(x, xr, in_w, wq, out_w, wo,
                                             fc1_w, w1, fc2_w, w2);

    // QKV projection (output tf32-rounded: feeds tensor-core attention)
    mma_gemm<false, false, true><<<dim3(3 * Ev / 128, Mv / 128), 128, GSMEM>>>(
        xr, wq, in_b, nullptr, qkv, Mv, 3 * Ev, Ev);

    // Tensor-core flash attention (causal + key padding); output tf32-rounded
    attn_kernel<<<dim3(Tv / 64, Hv, Bv), 128, ATT_SMEM>>>(qkv, attn);

    // Out projection + residual (residual = exact x)
    mma_gemm<true, false, false><<<dim3(Ev / 128, Mv / 128), 128, GSMEM>>>(
        attn, wo, out_b, x, y1, Mv, Ev, Ev);
    ln_kernel<true><<<Mv / 8, 256>>>(y1, ln1_w, ln1_b, x1, x1r);

    // FFN
    mma_gemm<false, true, true><<<dim3(FFv / 128, Mv / 128), 128, GSMEM>>>(
        x1r, w1, fc1_b, nullptr, hb, Mv, FFv, Ev);
    mma_gemm<true, false, false><<<dim3(Ev / 128, Mv / 128), 128, GSMEM>>>(
        hb, w2, fc2_b, x1, y2, Mv, Ev, FFv);
    ln_kernel<false><<<Mv / 8, 256>>>(y2, ln2_w, ln2_b, (float*)d_out, nullptr);

    (void)in_sizes; (void)n_in; (void)out_size;
}